// round 4
// baseline (speedup 1.0000x reference)
#include <cuda_runtime.h>
#include <cuda_bf16.h>
#include <cstddef>

// Problem constants (shapes fixed by the dataset)
#define NPTS   8192
#define DIM    256
#define KR     5      // kmeans runs
#define NC     64     // clusters per run
#define TK     8      // top_k
#define NITER  20

// ---------------- device scratch (static globals; no allocation) ----------------
__device__ float    g_sim[(size_t)NPTS * NPTS];          // 256 MB similarity matrix
__device__ unsigned g_bitmap[(size_t)NPTS * NPTS / 32];  // 8 MB adjacency bitmap
__device__ float    g_cent[KR * NC * DIM];
__device__ float    g_cnorm[KR * NC];
__device__ float    g_sums[KR * NC * DIM];
__device__ float    g_counts[KR * NC];
__device__ int      g_labels[KR * NPTS];
__device__ int      g_Iknn[NPTS * TK];
__device__ float    g_Dknn[NPTS * TK];

// ---------------- packed f32x2 helpers ----------------
__device__ __forceinline__ unsigned long long pack2(float lo, float hi) {
    unsigned long long d;
    asm("mov.b64 %0, {%1, %2};" : "=l"(d) : "f"(lo), "f"(hi));
    return d;
}
__device__ __forceinline__ unsigned long long dup2(float v) {
    unsigned long long d;
    asm("mov.b64 %0, {%1, %1};" : "=l"(d) : "f"(v));
    return d;
}
__device__ __forceinline__ void unpack2(unsigned long long d, float& lo, float& hi) {
    asm("mov.b64 {%0, %1}, %2;" : "=f"(lo), "=f"(hi) : "l"(d));
}
__device__ __forceinline__ void ffma2(unsigned long long& d, unsigned long long a,
                                      unsigned long long b) {
    asm("fma.rn.f32x2 %0, %1, %2, %0;" : "+l"(d) : "l"(a), "l"(b));
}

// ---------------- adjacency bitmap ----------------
__global__ void set_edges_kernel(const int* __restrict__ eidx, int E) {
    int t = blockIdx.x * blockDim.x + threadIdx.x;
    if (t < E) {
        int a = eidx[t];
        int b = eidx[E + t];
        unsigned code = (unsigned)a * NPTS + (unsigned)b;
        atomicOr(&g_bitmap[code >> 5], 1u << (code & 31));
    }
}

// ---------------- kmeans: init centroids (gather + norms); also zero accumulators ----------------
__global__ void kinit_kernel(const float* __restrict__ X, const int* __restrict__ init_idx) {
    int rc = blockIdx.x;               // 0..KR*NC-1
    int src = init_idx[rc];
    float v = X[(size_t)src * DIM + threadIdx.x];
    g_cent[(size_t)rc * DIM + threadIdx.x] = v;
    // zero accumulators for the first Lloyd step (update_kernel re-zeros thereafter)
    g_sums[(size_t)rc * DIM + threadIdx.x] = 0.0f;
    if (threadIdx.x == 0) g_counts[rc] = 0.0f;
    __shared__ float red[256];
    red[threadIdx.x] = v * v;
    __syncthreads();
    for (int s = 128; s > 0; s >>= 1) {
        if (threadIdx.x < s) red[threadIdx.x] += red[threadIdx.x + s];
        __syncthreads();
    }
    if (threadIdx.x == 0) g_cnorm[rc] = red[0];
}

// ---------------- kmeans: assign (argmin_c ||c||^2 - 2 x.c) ----------------
// grid (NPTS/64, KR), block 256. Computes 64 pts x 64 clusters dot tile.
// Inner product via packed f32x2 FFMA (2 MACs/instr).
__global__ void assign_kernel(const float* __restrict__ X) {
    int r = blockIdx.y;
    int pbase = blockIdx.x * 64;
    __shared__ float Xs[16][64];
    __shared__ float Cs[16][64];
    __shared__ float dots[64][65];
    __shared__ float cn[64];
    int tid = threadIdx.x;
    int ty = tid >> 4, tx = tid & 15;
    unsigned long long acc2[4][2];
#pragma unroll
    for (int i = 0; i < 4; i++)
#pragma unroll
        for (int j = 0; j < 2; j++) acc2[i][j] = 0ull;  // (+0.0f, +0.0f)
    int lrow = tid >> 2;
    int kq = (tid & 3) * 4;
    for (int k0 = 0; k0 < DIM; k0 += 16) {
        float4 a4 = *(const float4*)&X[(size_t)(pbase + lrow) * DIM + k0 + kq];
        float4 b4 = *(const float4*)&g_cent[(size_t)(r * NC + lrow) * DIM + k0 + kq];
        Xs[kq + 0][lrow] = a4.x; Xs[kq + 1][lrow] = a4.y;
        Xs[kq + 2][lrow] = a4.z; Xs[kq + 3][lrow] = a4.w;
        Cs[kq + 0][lrow] = b4.x; Cs[kq + 1][lrow] = b4.y;
        Cs[kq + 2][lrow] = b4.z; Cs[kq + 3][lrow] = b4.w;
        __syncthreads();
#pragma unroll
        for (int kk = 0; kk < 16; kk++) {
            unsigned long long a2[4], b2[2];
#pragma unroll
            for (int i = 0; i < 4; i++) a2[i] = dup2(Xs[kk][ty * 4 + i]);
#pragma unroll
            for (int j = 0; j < 2; j++) {
                float2 b = *(const float2*)&Cs[kk][tx * 4 + j * 2];
                b2[j] = pack2(b.x, b.y);
            }
#pragma unroll
            for (int i = 0; i < 4; i++)
#pragma unroll
                for (int j = 0; j < 2; j++) ffma2(acc2[i][j], a2[i], b2[j]);
        }
        __syncthreads();
    }
#pragma unroll
    for (int i = 0; i < 4; i++)
#pragma unroll
        for (int j = 0; j < 2; j++) {
            float lo, hi;
            unpack2(acc2[i][j], lo, hi);
            dots[ty * 4 + i][tx * 4 + j * 2 + 0] = lo;
            dots[ty * 4 + i][tx * 4 + j * 2 + 1] = hi;
        }
    if (tid < 64) cn[tid] = g_cnorm[r * NC + tid];
    __syncthreads();
    if (tid < 64) {
        int p = tid;
        float best = 1e30f;
        int bi = 0;
        for (int c = 0; c < NC; c++) {
            float d2 = cn[c] - 2.0f * dots[p][c];
            if (d2 < best) { best = d2; bi = c; }   // strict < -> first-min, matches jnp.argmin
        }
        g_labels[r * NPTS + pbase + p] = bi;
    }
}

// ---------------- kmeans: scatter segment sums (smem-accumulated) ----------------
// grid (NPTS/256, KR), block 256, dynamic smem = NC*DIM floats (+NC counts).
#define SCAT_PTS 256
__global__ void scatter_kernel(const float* __restrict__ X) {
    extern __shared__ float sh[];                // [NC][DIM] acc + [NC] counts
    float* acc = sh;                             // NC*DIM
    float* cnt = sh + NC * DIM;                  // NC
    int r = blockIdx.y;
    int pbase = blockIdx.x * SCAT_PTS;
    int tid = threadIdx.x;
#pragma unroll
    for (int c = 0; c < NC; c++) acc[c * DIM + tid] = 0.0f;
    if (tid < NC) cnt[tid] = 0.0f;
    __syncthreads();
    for (int p = 0; p < SCAT_PTS; p++) {
        int l = g_labels[r * NPTS + pbase + p];                   // uniform -> broadcast
        acc[l * DIM + tid] += X[(size_t)(pbase + p) * DIM + tid]; // conflict-free smem col
        if (tid == 0) cnt[l] += 1.0f;
    }
    __syncthreads();
#pragma unroll
    for (int c = 0; c < NC; c++)
        atomicAdd(&g_sums[(size_t)(r * NC + c) * DIM + tid], acc[c * DIM + tid]);
    if (tid < NC) atomicAdd(&g_counts[r * NC + tid], cnt[tid]);
}

// ---------------- kmeans: centroid update + norms; re-zero accumulators for next iter ----------------
__global__ void update_kernel() {
    int rc = blockIdx.x;
    float cnt = g_counts[rc];
    float v = g_cent[(size_t)rc * DIM + threadIdx.x];
    if (cnt > 0.0f) v = g_sums[(size_t)rc * DIM + threadIdx.x] / fmaxf(cnt, 1.0f);
    g_cent[(size_t)rc * DIM + threadIdx.x] = v;
    g_sums[(size_t)rc * DIM + threadIdx.x] = 0.0f;
    if (threadIdx.x == 0) g_counts[rc] = 0.0f;
    __shared__ float red[256];
    red[threadIdx.x] = v * v;
    __syncthreads();
    for (int s = 128; s > 0; s >>= 1) {
        if (threadIdx.x < s) red[threadIdx.x] += red[threadIdx.x + s];
        __syncthreads();
    }
    if (threadIdx.x == 0) g_cnorm[rc] = red[0];
}

// ---------------- big GEMM: sim = student @ teacher^T (+10 on diag) ----------------
// 128x128 tiles, Bk=8, 256 threads, 8x8 per-thread tile as 8x4 packed f32x2 accumulators.
__global__ void gemm_sim_kernel(const float* __restrict__ A, const float* __restrict__ B) {
    __shared__ float As[8][128];
    __shared__ float Bs[8][128];
    int bi = blockIdx.y * 128, bj = blockIdx.x * 128;
    int tid = threadIdx.x;
    int tx = tid & 15, ty = tid >> 4;
    unsigned long long acc2[8][4];
#pragma unroll
    for (int i = 0; i < 8; i++)
#pragma unroll
        for (int j = 0; j < 4; j++) acc2[i][j] = 0ull;  // (+0.0f, +0.0f)
    int lr = tid >> 1;
    int kq = (tid & 1) * 4;
    for (int k0 = 0; k0 < DIM; k0 += 8) {
        float4 a4 = *(const float4*)&A[(size_t)(bi + lr) * DIM + k0 + kq];
        float4 b4 = *(const float4*)&B[(size_t)(bj + lr) * DIM + k0 + kq];
        As[kq + 0][lr] = a4.x; As[kq + 1][lr] = a4.y;
        As[kq + 2][lr] = a4.z; As[kq + 3][lr] = a4.w;
        Bs[kq + 0][lr] = b4.x; Bs[kq + 1][lr] = b4.y;
        Bs[kq + 2][lr] = b4.z; Bs[kq + 3][lr] = b4.w;
        __syncthreads();
#pragma unroll
        for (int kk = 0; kk < 8; kk++) {
            unsigned long long a2[8], b2[4];
#pragma unroll
            for (int i = 0; i < 8; i++) a2[i] = dup2(As[kk][ty * 8 + i]);
#pragma unroll
            for (int j = 0; j < 4; j++) {
                float2 b = *(const float2*)&Bs[kk][tx * 8 + j * 2];
                b2[j] = pack2(b.x, b.y);
            }
#pragma unroll
            for (int i = 0; i < 8; i++)
#pragma unroll
                for (int j = 0; j < 4; j++) ffma2(acc2[i][j], a2[i], b2[j]);
        }
        __syncthreads();
    }
#pragma unroll
    for (int i = 0; i < 8; i++) {
        int gi = bi + ty * 8 + i;
#pragma unroll
        for (int j = 0; j < 4; j++) {
            int gj = bj + tx * 8 + j * 2;
            float lo, hi;
            unpack2(acc2[i][j], lo, hi);
            if (gi == gj) lo += 10.0f;
            if (gi == gj + 1) hi += 10.0f;
            float2 vv = make_float2(lo, hi);
            *(float2*)&g_sim[(size_t)gi * NPTS + gj] = vv;
        }
    }
}

// ---------------- top-8 per row ----------------
// one block (256 threads) per row; per-thread sorted top-8, then smem tournament merge
__global__ void topk_kernel() {
    int row = blockIdx.x;
    const float* s = g_sim + (size_t)row * NPTS;
    int tid = threadIdx.x;
    float v[TK];
    int id[TK];
#pragma unroll
    for (int t = 0; t < TK; t++) { v[t] = -1e30f; id[t] = 0x7fffffff; }
    for (int j = tid; j < NPTS; j += 256) {
        float x = s[j];
        if (x > v[TK - 1]) {
            v[TK - 1] = x; id[TK - 1] = j;
#pragma unroll
            for (int t = TK - 1; t > 0; t--) {
                if (v[t] > v[t - 1]) {
                    float tv = v[t]; v[t] = v[t - 1]; v[t - 1] = tv;
                    int ti = id[t]; id[t] = id[t - 1]; id[t - 1] = ti;
                }
            }
        }
    }
    __shared__ float sv[256 * TK];
    __shared__ int si[256 * TK];
#pragma unroll
    for (int t = 0; t < TK; t++) { sv[tid * TK + t] = v[t]; si[tid * TK + t] = id[t]; }
    __syncthreads();
    for (int half = 128; half >= 1; half >>= 1) {
        float ov[TK];
        int oi[TK];
        if (tid < half) {
            int ai = 0, bi = 0;
#pragma unroll
            for (int t = 0; t < TK; t++) {
                float av = sv[tid * TK + ai], bv = sv[(tid + half) * TK + bi];
                int aid = si[tid * TK + ai], bid = si[(tid + half) * TK + bi];
                bool takeA = (av > bv) || (av == bv && aid <= bid);  // stable: lower index first
                if (takeA) { ov[t] = av; oi[t] = aid; ai++; }
                else       { ov[t] = bv; oi[t] = bid; bi++; }
            }
#pragma unroll
            for (int t = 0; t < TK; t++) { sv[tid * TK + t] = ov[t]; si[tid * TK + t] = oi[t]; }
        }
        __syncthreads();
    }
    if (tid < TK) {
        g_Dknn[row * TK + tid] = sv[tid];
        g_Iknn[row * TK + tid] = si[tid];
    }
}

// ---------------- finalize: mask + outputs ----------------
// out layout: [I_knn (as float) | pos_mask (0/1) | D_knn], each NPTS*TK
__global__ void finalize_kernel(float* __restrict__ out) {
    int t = blockIdx.x * blockDim.x + threadIdx.x;   // 0..NPTS*TK-1
    if (t >= NPTS * TK) return;
    int i = t >> 3;
    int I = g_Iknn[t];
    unsigned code = (unsigned)i * NPTS + (unsigned)I;
    bool adj = (g_bitmap[code >> 5] >> (code & 31)) & 1u;
    bool close = false;
#pragma unroll
    for (int r = 0; r < KR; r++)
        close = close || (g_labels[r * NPTS + i] == g_labels[r * NPTS + I]);
    out[t] = (float)I;
    out[NPTS * TK + t] = (adj || close) ? 1.0f : 0.0f;
    out[2 * NPTS * TK + t] = g_Dknn[t];
}

// ---------------- launch ----------------
extern "C" void kernel_launch(void* const* d_in, const int* in_sizes, int n_in,
                              void* d_out, int out_size) {
    const float* student = (const float*)d_in[0];
    const float* teacher = (const float*)d_in[1];
    const int* eidx      = (const int*)d_in[2];
    const int* kinit_idx = (const int*)d_in[3];
    // d_in[4] = top_k (known 8; hardcoded as TK)
    float* out = (float*)d_out;
    int E = in_sizes[2] / 2;

    void* bmp_p;
    cudaGetSymbolAddress(&bmp_p, g_bitmap);

    // dynamic smem for scatter: NC*DIM acc + NC counts
    const size_t scat_smem = (size_t)(NC * DIM + NC) * sizeof(float);
    cudaFuncSetAttribute(scatter_kernel, cudaFuncAttributeMaxDynamicSharedMemorySize,
                         (int)scat_smem);

    // adjacency bitmap
    cudaMemsetAsync(bmp_p, 0, (size_t)NPTS * NPTS / 8);
    set_edges_kernel<<<(E + 255) / 256, 256>>>(eidx, E);

    // kmeans (KR parallel runs, NITER sequential Lloyd steps)
    kinit_kernel<<<KR * NC, 256>>>(teacher, kinit_idx);
    for (int it = 0; it < NITER; it++) {
        assign_kernel<<<dim3(NPTS / 64, KR), 256>>>(teacher);
        scatter_kernel<<<dim3(NPTS / SCAT_PTS, KR), 256, scat_smem>>>(teacher);
        update_kernel<<<KR * NC, 256>>>();
    }
    assign_kernel<<<dim3(NPTS / 64, KR), 256>>>(teacher);  // final labels

    // similarity + top-k
    gemm_sim_kernel<<<dim3(NPTS / 128, NPTS / 128), 256>>>(student, teacher);
    topk_kernel<<<NPTS, 256>>>();

    // outputs
    finalize_kernel<<<(NPTS * TK + 255) / 256, 256>>>(out);
}